// round 6
// baseline (speedup 1.0000x reference)
#include <cuda_runtime.h>

#define NPERSEG 1024
#define STEP     256
#define SEQ    16384
#define NWIN      61
#define BATCH   1024
#define THREADS  512

#define CTILE   2048                 // samples per column block
#define CF4     (CTILE / 4)          // 512 float4 per column block = THREADS
#define RTILE   4                    // rows per CTA
#define NCB     (SEQ / CTILE)        // 8 column blocks
#define NRB     (BATCH / RTILE)      // 256 row blocks

// Per-(row, col-block) partial sums, written exactly once per slot.
__device__ float g_pre[BATCH * NCB];
__device__ float g_pim[BATCH * NCB];

// CTA (cb, rb): rows [rb*4, rb*4+4) x samples [cb*2048, +2048), single pass.
// Thread tid owns float4 index l=tid. Its 4 weights depend only on
// (tid & 63) and wbase = cb*8 + (tid>>6)  ->  held in 8 registers.
__global__ __launch_bounds__(THREADS) void welch_main_kernel(
    const float4* __restrict__ in,
    const float*  __restrict__ freqs)
{
    __shared__ float2 s_cs[NPERSEG];   // 8 KB: (cos, sin) of 2*pi*freqs[p]
    __shared__ float  s_red[128];      // warp partials: 16 warps x 8 values

    const int cb  = blockIdx.x;
    const int rb  = blockIdx.y;
    const int tid = threadIdx.x;
    const float TWO_PI = 6.283185307179586476925f;

    // --- Stage 1: sincos table (2 bins per thread) ---
    #pragma unroll
    for (int k = 0; k < 2; ++k) {
        int p = tid + k * THREADS;
        float sn, cs;
        sincosf(TWO_PI * freqs[p], &sn, &cs);
        s_cs[p] = make_float2(cs, sn);
    }
    __syncthreads();

    // --- Stage 2: per-thread weight registers ---
    // sample s = cb*2048 + 4*tid + c;  pbase = 4*(tid&63)+c;
    // window w = (s>>8) - k = wbase - k, valid iff 0 <= w < 61.
    const int pb    = 4 * (tid & 63);
    const int wbase = cb * 8 + (tid >> 6);        // warp-uniform
    float wre[4] = {0.f, 0.f, 0.f, 0.f};
    float wim[4] = {0.f, 0.f, 0.f, 0.f};
    #pragma unroll
    for (int k = 0; k < 4; ++k) {
        if (k <= wbase && (wbase - k) < NWIN) {   // uniform predicate
            #pragma unroll
            for (int c = 0; c < 4; ++c) {
                float2 t = s_cs[pb + c + k * STEP];
                wre[c] += t.x;
                wim[c] -= t.y;
            }
        }
    }
    const float inv = 1.0f / (float)NWIN;
    #pragma unroll
    for (int c = 0; c < 4; ++c) { wre[c] *= inv; wim[c] *= inv; }

    // --- Stage 3: straight-line stream of 4 rows (4 batched LDG.128) ---
    const int row0 = rb * RTILE;
    const float4* __restrict__ base =
        in + (size_t)row0 * (SEQ / 4) + cb * CF4 + tid;

    float4 x[RTILE];
    #pragma unroll
    for (int r = 0; r < RTILE; ++r)
        x[r] = __ldcg(base + (size_t)r * (SEQ / 4));

    float accre[RTILE], accim[RTILE];
    #pragma unroll
    for (int r = 0; r < RTILE; ++r) {
        accre[r] = x[r].x * wre[0];
        accre[r] = fmaf(x[r].y, wre[1], accre[r]);
        accre[r] = fmaf(x[r].z, wre[2], accre[r]);
        accre[r] = fmaf(x[r].w, wre[3], accre[r]);
        accim[r] = x[r].x * wim[0];
        accim[r] = fmaf(x[r].y, wim[1], accim[r]);
        accim[r] = fmaf(x[r].z, wim[2], accim[r]);
        accim[r] = fmaf(x[r].w, wim[3], accim[r]);
    }

    // --- Stage 4: reduce. Warp-shuffle, then tiny cross-warp pass ---
    #pragma unroll
    for (int off = 16; off > 0; off >>= 1) {
        #pragma unroll
        for (int r = 0; r < RTILE; ++r) {
            accre[r] += __shfl_xor_sync(0xffffffffu, accre[r], off);
            accim[r] += __shfl_xor_sync(0xffffffffu, accim[r], off);
        }
    }
    const int w    = tid >> 5;       // 16 warps
    const int lane = tid & 31;
    if (lane == 0) {
        #pragma unroll
        for (int r = 0; r < RTILE; ++r) {
            s_red[w * 8 + r * 2 + 0] = accre[r];
            s_red[w * 8 + r * 2 + 1] = accim[r];
        }
    }
    __syncthreads();

    if (tid < 8) {                   // tid -> (row r = tid>>1, comp = tid&1)
        float v = 0.f;
        #pragma unroll
        for (int ww = 0; ww < 16; ++ww)
            v += s_red[ww * 8 + tid];
        const int r = tid >> 1;
        if ((tid & 1) == 0) g_pre[(row0 + r) * NCB + cb] = v;
        else                g_pim[(row0 + r) * NCB + cb] = v;
    }
}

__global__ void epilogue_kernel(const float* __restrict__ fc_w,
                                const float* __restrict__ fc_b,
                                float* __restrict__ out)
{
    int b = blockIdx.x * blockDim.x + threadIdx.x;
    if (b >= BATCH) return;
    float fr = 0.f, fi = 0.f;
    #pragma unroll
    for (int c = 0; c < NCB; ++c) {
        fr += g_pre[b * NCB + c];
        fi += g_pim[b * NCB + c];
    }
    float psd = fr * fr + fi * fi;
    out[b] = fmaf(psd, fc_w[0], fc_b[0]);
}

extern "C" void kernel_launch(void* const* d_in, const int* in_sizes, int n_in,
                              void* d_out, int out_size) {
    const float* input = (const float*)d_in[0];   // (1024, 16384) f32
    const float* freqs = (const float*)d_in[1];   // (1024,) f32
    const float* fc_w  = (const float*)d_in[2];   // (1,1) f32
    const float* fc_b  = (const float*)d_in[3];   // (1,) f32
    float* out = (float*)d_out;                   // (1024, 1) f32

    welch_main_kernel<<<dim3(NCB, NRB), THREADS>>>((const float4*)input, freqs);
    epilogue_kernel<<<4, 256>>>(fc_w, fc_b, out);
}

// round 7
// speedup vs baseline: 2.1463x; 2.1463x over previous
#include <cuda_runtime.h>

#define SEQ    16384
#define BATCH   1024
#define NWIN      61
#define STEP     256
#define TPB      128                 // threads per CTA (main)
#define GPT      (SEQ / 4 / TPB)     // 32 float4 groups per thread

// Weight table: 8 sets x 256 samples (prefix P[0..3] = sets 0..3,
// suffix S[0..3] = sets 4..7), pre-scaled by 1/61, im = -sin/61.
__device__ float g_Wre[8 * 256];
__device__ float g_Wim[8 * 256];

// ---- Kernel 1: build prefix/suffix weight table (1024 sincosf total) ----
__global__ void table_kernel(const float* __restrict__ freqs) {
    const int p0 = threadIdx.x;                 // 0..255
    const float TWO_PI = 6.283185307179586476925f;
    const float inv = 1.0f / (float)NWIN;
    float cr[4], ci[4];
    #pragma unroll
    for (int k = 0; k < 4; ++k) {
        float sn, cs;
        sincosf(TWO_PI * freqs[p0 + STEP * k], &sn, &cs);
        cr[k] = cs * inv;
        ci[k] = -sn * inv;
    }
    float pr = 0.f, pi = 0.f;
    #pragma unroll
    for (int k = 0; k < 4; ++k) {               // prefixes P[k]
        pr += cr[k]; pi += ci[k];
        g_Wre[k * 256 + p0] = pr;
        g_Wim[k * 256 + p0] = pi;
    }
    float sr = 0.f, si = 0.f;
    #pragma unroll
    for (int k = 3; k >= 0; --k) {              // suffixes S[k]
        sr += cr[k]; si += ci[k];
        g_Wre[(4 + k) * 256 + p0] = sr;
        g_Wim[(4 + k) * 256 + p0] = si;
    }
}

// ---- Kernel 2: one CTA per batch row; whole grid resident in one wave ----
// Thread tid owns float4 groups l = tid + 128g (g=0..31); sample s = 4l+c.
// s mod 256 = 4*(tid&63)+c (g-invariant); wbase = s>>8 = (tid>>6) + 2g.
// Valid windows: wbase<=60 -> prefix P[min(3,wbase)]; else suffix S[wbase-60].
//   g==0  -> P[q]      (wbase = q, q = tid>>6 in {0,1})
//   g==1  -> P[2+q]
//   g==2..29 -> P[3]   (interior, full sum)
//   g==30 -> S[q]      (S[0] == full sum, correct for wbase=60)
//   g==31 -> S[2+q]
__global__ __launch_bounds__(TPB, 7) void welch_kernel(
    const float4* __restrict__ in,
    const float*  __restrict__ fc_w,
    const float*  __restrict__ fc_b,
    float*        __restrict__ out)
{
    const int tid = threadIdx.x;
    const int b   = blockIdx.x;
    const int q   = tid >> 6;        // 0 or 1
    const int j   = tid & 63;        // float4 index within 256-sample period

    const float4* __restrict__ Wre4 = (const float4*)g_Wre;
    const float4* __restrict__ Wim4 = (const float4*)g_Wim;

    // 5 weight sets, 40 registers, held for the whole kernel. All L2 hits.
    const float4 Ar = Wre4[(0 + q) * 64 + j], Ai = Wim4[(0 + q) * 64 + j];
    const float4 Br = Wre4[(2 + q) * 64 + j], Bi = Wim4[(2 + q) * 64 + j];
    const float4 Ir = Wre4[(3    ) * 64 + j], Ii = Wim4[(3    ) * 64 + j];
    const float4 Cr = Wre4[(4 + q) * 64 + j], Ci = Wim4[(4 + q) * 64 + j];
    const float4 Dr = Wre4[(6 + q) * 64 + j], Di = Wim4[(6 + q) * 64 + j];

    const float4* __restrict__ row = in + (size_t)b * (SEQ / 4) + tid;

    float re0 = 0.f, re1 = 0.f, im0 = 0.f, im1 = 0.f;

    #pragma unroll
    for (int bt = 0; bt < 8; ++bt) {
        float4 x[4];
        #pragma unroll
        for (int i = 0; i < 4; ++i)
            x[i] = __ldcg(row + (4 * bt + i) * TPB);

        #pragma unroll
        for (int i = 0; i < 4; ++i) {
            const int g = 4 * bt + i;   // literal after unroll
            const float4 wr = (g == 0) ? Ar : (g == 1) ? Br :
                              (g == 30) ? Cr : (g == 31) ? Dr : Ir;
            const float4 wi = (g == 0) ? Ai : (g == 1) ? Bi :
                              (g == 30) ? Ci : (g == 31) ? Di : Ii;
            if (i & 1) {
                re1 = fmaf(x[i].x, wr.x, re1); re1 = fmaf(x[i].y, wr.y, re1);
                re1 = fmaf(x[i].z, wr.z, re1); re1 = fmaf(x[i].w, wr.w, re1);
                im1 = fmaf(x[i].x, wi.x, im1); im1 = fmaf(x[i].y, wi.y, im1);
                im1 = fmaf(x[i].z, wi.z, im1); im1 = fmaf(x[i].w, wi.w, im1);
            } else {
                re0 = fmaf(x[i].x, wr.x, re0); re0 = fmaf(x[i].y, wr.y, re0);
                re0 = fmaf(x[i].z, wr.z, re0); re0 = fmaf(x[i].w, wr.w, re0);
                im0 = fmaf(x[i].x, wi.x, im0); im0 = fmaf(x[i].y, wi.y, im0);
                im0 = fmaf(x[i].z, wi.z, im0); im0 = fmaf(x[i].w, wi.w, im0);
            }
        }
    }

    float re = re0 + re1;
    float im = im0 + im1;

    // Block reduce: 4 warps -> 1 value.
    #pragma unroll
    for (int off = 16; off > 0; off >>= 1) {
        re += __shfl_xor_sync(0xffffffffu, re, off);
        im += __shfl_xor_sync(0xffffffffu, im, off);
    }
    __shared__ float s[8];
    const int w    = tid >> 5;
    const int lane = tid & 31;
    if (lane == 0) { s[w] = re; s[4 + w] = im; }
    __syncthreads();

    if (tid == 0) {
        float fr = (s[0] + s[1]) + (s[2] + s[3]);
        float fi = (s[4] + s[5]) + (s[6] + s[7]);
        float psd = fr * fr + fi * fi;
        out[b] = fmaf(psd, fc_w[0], fc_b[0]);
    }
}

extern "C" void kernel_launch(void* const* d_in, const int* in_sizes, int n_in,
                              void* d_out, int out_size) {
    const float* input = (const float*)d_in[0];   // (1024, 16384) f32
    const float* freqs = (const float*)d_in[1];   // (1024,) f32
    const float* fc_w  = (const float*)d_in[2];   // (1,1) f32
    const float* fc_b  = (const float*)d_in[3];   // (1,) f32
    float* out = (float*)d_out;                   // (1024, 1) f32

    table_kernel<<<1, 256>>>(freqs);
    welch_kernel<<<BATCH, TPB>>>((const float4*)input, fc_w, fc_b, out);
}